// round 8
// baseline (speedup 1.0000x reference)
#include <cuda_runtime.h>
#include <cuda_bf16.h>
#include <stdint.h>

#define BB 16
#define LLEN 2048
#define DD 64
#define TQ 128
#define NTH 256
#define STRIDE 144                  // smem row stride bytes (72 bf16, conflict-free)
#define BUFB (64 * STRIDE)          // one 64-row half (hi or lo) = 9216 B
#define TILEB (2 * BUFB)            // hi+lo buffer = 18432 B

#define OFF_V 0                     // region A: V double buffer (pass 2)
#define OFF_K (2 * TILEB)           // region B: K double buffer (pass 1)
#define SMEM_TOTAL (4 * TILEB)      // 73728 B

#define NEG_INF __int_as_float(0xff800000)

// ---------------- helpers ----------------
__device__ __forceinline__ uint32_t smem_u32(const void* p) {
    uint32_t a;
    asm("{ .reg .u64 t; cvta.to.shared.u64 t, %1; cvt.u32.u64 %0, t; }" : "=r"(a) : "l"(p));
    return a;
}
__device__ __forceinline__ void ldsm4(uint32_t a, uint32_t r[4]) {
    asm volatile("ldmatrix.sync.aligned.m8n8.x4.shared.b16 {%0,%1,%2,%3}, [%4];"
                 : "=r"(r[0]), "=r"(r[1]), "=r"(r[2]), "=r"(r[3]) : "r"(a));
}
__device__ __forceinline__ void ldsm4t(uint32_t a, uint32_t r[4]) {
    asm volatile("ldmatrix.sync.aligned.m8n8.x4.trans.shared.b16 {%0,%1,%2,%3}, [%4];"
                 : "=r"(r[0]), "=r"(r[1]), "=r"(r[2]), "=r"(r[3]) : "r"(a));
}
__device__ __forceinline__ void mma_bf16(float* d, const uint32_t* a, uint32_t b0, uint32_t b1) {
    asm volatile("mma.sync.aligned.m16n8k16.row.col.f32.bf16.bf16.f32 "
                 "{%0,%1,%2,%3}, {%4,%5,%6,%7}, {%8,%9}, {%0,%1,%2,%3};"
                 : "+f"(d[0]), "+f"(d[1]), "+f"(d[2]), "+f"(d[3])
                 : "r"(a[0]), "r"(a[1]), "r"(a[2]), "r"(a[3]), "r"(b0), "r"(b1));
}
__device__ __forceinline__ void split2(float a, float b, uint32_t& hi, uint32_t& lo) {
    __nv_bfloat16 ah = __float2bfloat16(a);
    __nv_bfloat16 bh = __float2bfloat16(b);
    float ar = a - __bfloat162float(ah);
    float br = b - __bfloat162float(bh);
    __nv_bfloat162 H; H.x = ah; H.y = bh;
    __nv_bfloat162 L; L.x = __float2bfloat16(ar); L.y = __float2bfloat16(br);
    hi = *reinterpret_cast<uint32_t*>(&H);
    lo = *reinterpret_cast<uint32_t*>(&L);
}
__device__ __forceinline__ void load_regs4(const float* __restrict__ g, float4* r, int tid) {
    #pragma unroll
    for (int i = 0; i < 4; ++i)
        r[i] = reinterpret_cast<const float4*>(g)[tid + i * NTH];
}
__device__ __forceinline__ void store_split4(const float4* r, char* hi, char* lo, int tid) {
    #pragma unroll
    for (int i = 0; i < 4; ++i) {
        int idx = tid + i * NTH;
        float4 t = r[i];
        uint32_t h01, l01, h23, l23;
        split2(t.x, t.y, h01, l01);
        split2(t.z, t.w, h23, l23);
        int rr = idx >> 4;
        int c8 = (idx & 15) << 3;
        *reinterpret_cast<uint2*>(hi + rr * STRIDE + c8) = make_uint2(h01, h23);
        *reinterpret_cast<uint2*>(lo + rr * STRIDE + c8) = make_uint2(l01, l23);
    }
}

__global__ __launch_bounds__(NTH, 3)
void attn_mma_kernel(const float* __restrict__ qg,
                     const float* __restrict__ kg,
                     const float* __restrict__ vg,
                     const int* __restrict__ diag,
                     const int* __restrict__ maskb,
                     float* __restrict__ outp,
                     float* __restrict__ attn)
{
    extern __shared__ __align__(16) char smem[];
    const int tid  = threadIdx.x;
    const int wid  = tid >> 5;
    const int lane = tid & 31;
    const int qt   = lane & 3;
    const int b    = blockIdx.y;
    const int q0   = blockIdx.x * TQ;

    const uint32_t sb = smem_u32(smem);
    const float* kbase = kg + (size_t)b * LLEN * DD;
    const float* vbase = vg + (size_t)b * LLEN * DD;

    const int r0l = wid * 16 + (lane >> 2);          // this thread's row0 (row1 = +8)
    const size_t g0 = (size_t)b * LLEN + q0 + r0l;
    const int* m0p = maskb + g0 * LLEN;
    const int* m1p = m0p + (size_t)8 * LLEN;
    const int* d0p = diag + g0 * LLEN;
    const int* d1p = d0p + (size_t)8 * LLEN;
    float* a0p = attn + g0 * LLEN;
    float* a1p = a0p + (size_t)8 * LLEN;

    // ---- Q fragments loaded straight from global into registers (scaled 1/8) ----
    uint32_t qfh[16], qfl[16];
    {
        const float* q0p = qg + g0 * DD;
        const float* q1p = q0p + 8 * DD;
        #pragma unroll
        for (int kc = 0; kc < 4; ++kc) {
            const int c = kc * 16 + qt * 2;
            float2 x0 = *reinterpret_cast<const float2*>(q0p + c);
            float2 x1 = *reinterpret_cast<const float2*>(q1p + c);
            float2 x2 = *reinterpret_cast<const float2*>(q0p + c + 8);
            float2 x3 = *reinterpret_cast<const float2*>(q1p + c + 8);
            split2(x0.x * 0.125f, x0.y * 0.125f, qfh[4 * kc + 0], qfl[4 * kc + 0]);
            split2(x1.x * 0.125f, x1.y * 0.125f, qfh[4 * kc + 1], qfl[4 * kc + 1]);
            split2(x2.x * 0.125f, x2.y * 0.125f, qfh[4 * kc + 2], qfl[4 * kc + 2]);
            split2(x3.x * 0.125f, x3.y * 0.125f, qfh[4 * kc + 3], qfl[4 * kc + 3]);
        }
    }

    // ldmatrix per-lane address components (relative to buffer base)
    const uint32_t boff = (uint32_t)(((((lane >> 4) & 1) * 8) + (lane & 7)) * STRIDE
                                     + ((lane >> 3) & 1) * 16);
    const uint32_t voff = (uint32_t)(((((lane >> 3) & 1) * 8) + (lane & 7)) * STRIDE
                                     + ((lane >> 4) & 1) * 16);

    // preload K tile 0 and V tile 0 (separate regions, both buffer 0)
    {
        float4 r[4];
        load_regs4(kbase, r, tid);
        store_split4(r, smem + OFF_K, smem + OFF_K + BUFB, tid);
        float4 s[4];
        load_regs4(vbase, s, tid);
        store_split4(s, smem + OFF_V, smem + OFF_V + BUFB, tid);
    }

    float m0 = -3.0e38f, m1 = -3.0e38f, l0 = 0.0f, l1 = 0.0f;

    // ============ PASS 1: S = QK^T, masks, raw-score write, online stats ============
    for (int kt = 0; kt < 32; ++kt) {
        const int k0 = kt * 64;
        float4 knext[4];
        if (kt + 1 < 32)
            load_regs4(kbase + (size_t)(k0 + 64) * DD, knext, tid);
        __syncthreads();                 // buf[kt&1] visible; prior readers done

        const int pb = kt & 1;
        const uint32_t kh_a = sb + OFF_K + pb * TILEB + boff;
        const uint32_t kl_a = kh_a + BUFB;

        float acc[8][4];
        #pragma unroll
        for (int nt = 0; nt < 8; ++nt)
            #pragma unroll
            for (int i = 0; i < 4; ++i) acc[nt][i] = 0.0f;

        #pragma unroll
        for (int kc = 0; kc < 4; ++kc) {
            #pragma unroll
            for (int p = 0; p < 4; ++p) {
                uint32_t kh4[4], kl4[4];
                ldsm4(kh_a + p * 16 * STRIDE + kc * 32, kh4);
                ldsm4(kl_a + p * 16 * STRIDE + kc * 32, kl4);
                mma_bf16(acc[2 * p],     qfh + 4 * kc, kh4[0], kh4[1]);
                mma_bf16(acc[2 * p],     qfh + 4 * kc, kl4[0], kl4[1]);
                mma_bf16(acc[2 * p],     qfl + 4 * kc, kh4[0], kh4[1]);
                mma_bf16(acc[2 * p + 1], qfh + 4 * kc, kh4[2], kh4[3]);
                mma_bf16(acc[2 * p + 1], qfh + 4 * kc, kl4[2], kl4[3]);
                mma_bf16(acc[2 * p + 1], qfl + 4 * kc, kh4[2], kh4[3]);
            }
        }
        if (kt + 1 < 32)
            store_split4(knext, smem + OFF_K + (pb ^ 1) * TILEB,
                         smem + OFF_K + (pb ^ 1) * TILEB + BUFB, tid);

        // ---- epilogue: masks row0 then row1, raw-score writes (streaming), stats ----
        float t0 = -3.0e38f, t1 = -3.0e38f;
        {
            int2 M[8], D2[8];
            #pragma unroll
            for (int nt = 0; nt < 8; ++nt) {
                const int cb = k0 + nt * 8 + qt * 2;
                M[nt]  = __ldcs(reinterpret_cast<const int2*>(m0p + cb));
                D2[nt] = __ldcs(reinterpret_cast<const int2*>(d0p + cb));
            }
            #pragma unroll
            for (int nt = 0; nt < 8; ++nt) {
                float s0 = acc[nt][0], s1 = acc[nt][1];
                if (M[nt].x)       s0 = NEG_INF;
                if (D2[nt].x == 0) s0 = -1.0e32f;
                if (M[nt].y)       s1 = NEG_INF;
                if (D2[nt].y == 0) s1 = -1.0e32f;
                __stcs(reinterpret_cast<float2*>(a0p + k0 + nt * 8 + qt * 2),
                       make_float2(s0, s1));
                acc[nt][0] = s0; acc[nt][1] = s1;
                t0 = fmaxf(t0, fmaxf(s0, s1));
            }
        }
        {
            int2 M[8], D2[8];
            #pragma unroll
            for (int nt = 0; nt < 8; ++nt) {
                const int cb = k0 + nt * 8 + qt * 2;
                M[nt]  = __ldcs(reinterpret_cast<const int2*>(m1p + cb));
                D2[nt] = __ldcs(reinterpret_cast<const int2*>(d1p + cb));
            }
            #pragma unroll
            for (int nt = 0; nt < 8; ++nt) {
                float s2 = acc[nt][2], s3 = acc[nt][3];
                if (M[nt].x)       s2 = NEG_INF;
                if (D2[nt].x == 0) s2 = -1.0e32f;
                if (M[nt].y)       s3 = NEG_INF;
                if (D2[nt].y == 0) s3 = -1.0e32f;
                __stcs(reinterpret_cast<float2*>(a1p + k0 + nt * 8 + qt * 2),
                       make_float2(s2, s3));
                acc[nt][2] = s2; acc[nt][3] = s3;
                t1 = fmaxf(t1, fmaxf(s2, s3));
            }
        }
        t0 = fmaxf(t0, __shfl_xor_sync(0xffffffffu, t0, 1));
        t0 = fmaxf(t0, __shfl_xor_sync(0xffffffffu, t0, 2));
        t1 = fmaxf(t1, __shfl_xor_sync(0xffffffffu, t1, 1));
        t1 = fmaxf(t1, __shfl_xor_sync(0xffffffffu, t1, 2));
        const float mn0 = fmaxf(m0, t0);
        const float mn1 = fmaxf(m1, t1);
        float e0 = 0.0f, e1 = 0.0f;
        #pragma unroll
        for (int nt = 0; nt < 8; ++nt) {
            e0 += __expf(acc[nt][0] - mn0) + __expf(acc[nt][1] - mn0);
            e1 += __expf(acc[nt][2] - mn1) + __expf(acc[nt][3] - mn1);
        }
        e0 += __shfl_xor_sync(0xffffffffu, e0, 1);
        e0 += __shfl_xor_sync(0xffffffffu, e0, 2);
        e1 += __shfl_xor_sync(0xffffffffu, e1, 1);
        e1 += __shfl_xor_sync(0xffffffffu, e1, 2);
        l0 = l0 * __expf(m0 - mn0) + e0;  m0 = mn0;
        l1 = l1 * __expf(m1 - mn1) + e1;  m1 = mn1;
    }

    const float rinv0 = 1.0f / l0;
    const float rinv1 = 1.0f / l1;

    float oacc[8][4];
    #pragma unroll
    for (int nt = 0; nt < 8; ++nt)
        #pragma unroll
        for (int i = 0; i < 4; ++i) oacc[nt][i] = 0.0f;

    // ============ PASS 2: readback scores, probs write, O += P V ============
    for (int kt = 0; kt < 32; ++kt) {
        const int k0 = kt * 64;
        float4 vnext[4];
        if (kt + 1 < 32)
            load_regs4(vbase + (size_t)(k0 + 64) * DD, vnext, tid);

        // score loads for THIS tile (same-thread data from pass 1) — issue pre-barrier
        float2 sx0[4], sy0[4], sx1[4], sy1[4];
        #pragma unroll
        for (int kc2 = 0; kc2 < 4; ++kc2) {
            const int cA = k0 + kc2 * 16 + qt * 2;
            sx0[kc2] = __ldcs(reinterpret_cast<const float2*>(a0p + cA));
            sy0[kc2] = __ldcs(reinterpret_cast<const float2*>(a0p + cA + 8));
            sx1[kc2] = __ldcs(reinterpret_cast<const float2*>(a1p + cA));
            sy1[kc2] = __ldcs(reinterpret_cast<const float2*>(a1p + cA + 8));
        }
        __syncthreads();                 // V buf[kt&1] visible; prior readers done

        // exp + probs write + P fragments
        uint32_t ph[16], pl[16];
        #pragma unroll
        for (int kc2 = 0; kc2 < 4; ++kc2) {
            const int cA = k0 + kc2 * 16 + qt * 2;
            float p00 = __expf(sx0[kc2].x - m0) * rinv0;
            float p01 = __expf(sx0[kc2].y - m0) * rinv0;
            float p02 = __expf(sy0[kc2].x - m0) * rinv0;
            float p03 = __expf(sy0[kc2].y - m0) * rinv0;
            float p10 = __expf(sx1[kc2].x - m1) * rinv1;
            float p11 = __expf(sx1[kc2].y - m1) * rinv1;
            float p12 = __expf(sy1[kc2].x - m1) * rinv1;
            float p13 = __expf(sy1[kc2].y - m1) * rinv1;
            __stcs(reinterpret_cast<float2*>(a0p + cA),     make_float2(p00, p01));
            __stcs(reinterpret_cast<float2*>(a0p + cA + 8), make_float2(p02, p03));
            __stcs(reinterpret_cast<float2*>(a1p + cA),     make_float2(p10, p11));
            __stcs(reinterpret_cast<float2*>(a1p + cA + 8), make_float2(p12, p13));
            split2(p00, p01, ph[4 * kc2 + 0], pl[4 * kc2 + 0]);   // row0, k-lo
            split2(p10, p11, ph[4 * kc2 + 1], pl[4 * kc2 + 1]);   // row1, k-lo
            split2(p02, p03, ph[4 * kc2 + 2], pl[4 * kc2 + 2]);   // row0, k-hi
            split2(p12, p13, ph[4 * kc2 + 3], pl[4 * kc2 + 3]);   // row1, k-hi
        }

        const int pb = kt & 1;
        const uint32_t vh_a = sb + OFF_V + pb * TILEB + voff;
        const uint32_t vl_a = vh_a + BUFB;
        #pragma unroll
        for (int kc2 = 0; kc2 < 4; ++kc2) {
            #pragma unroll
            for (int p = 0; p < 4; ++p) {
                uint32_t vh4[4], vl4[4];
                ldsm4t(vh_a + kc2 * 16 * STRIDE + p * 32, vh4);
                ldsm4t(vl_a + kc2 * 16 * STRIDE + p * 32, vl4);
                mma_bf16(oacc[2 * p],     ph + 4 * kc2, vh4[0], vh4[1]);
                mma_bf16(oacc[2 * p],     ph + 4 * kc2, vl4[0], vl4[1]);
                mma_bf16(oacc[2 * p],     pl + 4 * kc2, vh4[0], vh4[1]);
                mma_bf16(oacc[2 * p + 1], ph + 4 * kc2, vh4[2], vh4[3]);
                mma_bf16(oacc[2 * p + 1], ph + 4 * kc2, vl4[2], vl4[3]);
                mma_bf16(oacc[2 * p + 1], pl + 4 * kc2, vh4[2], vh4[3]);
            }
        }
        if (kt + 1 < 32)
            store_split4(vnext, smem + OFF_V + (pb ^ 1) * TILEB,
                         smem + OFF_V + (pb ^ 1) * TILEB + BUFB, tid);
    }

    // ---- write output ----
    float* o0 = outp + g0 * DD;
    float* o1 = o0 + (size_t)8 * DD;
    #pragma unroll
    for (int nt = 0; nt < 8; ++nt) {
        const int cb = nt * 8 + qt * 2;
        __stcs(reinterpret_cast<float2*>(o0 + cb), make_float2(oacc[nt][0], oacc[nt][1]));
        __stcs(reinterpret_cast<float2*>(o1 + cb), make_float2(oacc[nt][2], oacc[nt][3]));
    }
}

extern "C" void kernel_launch(void* const* d_in, const int* in_sizes, int n_in,
                              void* d_out, int out_size)
{
    const float* q    = (const float*)d_in[0];
    const float* k    = (const float*)d_in[1];
    const float* v    = (const float*)d_in[2];
    const int*   diag = (const int*)d_in[3];
    const int*   mask = (const int*)d_in[4];

    float* out  = (float*)d_out;                     // [B, L, D]
    float* attn = out + (size_t)BB * LLEN * DD;      // [B, L, L]

    cudaFuncSetAttribute(attn_mma_kernel,
                         cudaFuncAttributeMaxDynamicSharedMemorySize, SMEM_TOTAL);
    dim3 grid(LLEN / TQ, BB);
    attn_mma_kernel<<<grid, NTH, SMEM_TOTAL>>>(q, k, v, diag, mask, out, attn);
}

// round 9
// speedup vs baseline: 1.6427x; 1.6427x over previous
#include <cuda_runtime.h>
#include <cuda_bf16.h>
#include <stdint.h>

#define BB 16
#define LLEN 2048
#define DD 64
#define TQ 128
#define NTH 256
#define STRIDE 144                  // smem row stride bytes (72 bf16, conflict-free)
#define BUFB (64 * STRIDE)          // one 64-row half (hi or lo) = 9216 B
#define TILEB (2 * BUFB)            // hi+lo buffer = 18432 B

#define OFF_V 0                     // region A: V double buffer (pass 2)
#define OFF_K (2 * TILEB)           // region B: K double buffer (pass 1)
#define SMEM_TOTAL (4 * TILEB)      // 73728 B

#define NEG_INF __int_as_float(0xff800000)

// ---------------- helpers ----------------
__device__ __forceinline__ uint32_t smem_u32(const void* p) {
    uint32_t a;
    asm("{ .reg .u64 t; cvta.to.shared.u64 t, %1; cvt.u32.u64 %0, t; }" : "=r"(a) : "l"(p));
    return a;
}
__device__ __forceinline__ void ldsm4(uint32_t a, uint32_t r[4]) {
    asm volatile("ldmatrix.sync.aligned.m8n8.x4.shared.b16 {%0,%1,%2,%3}, [%4];"
                 : "=r"(r[0]), "=r"(r[1]), "=r"(r[2]), "=r"(r[3]) : "r"(a));
}
__device__ __forceinline__ void ldsm4t(uint32_t a, uint32_t r[4]) {
    asm volatile("ldmatrix.sync.aligned.m8n8.x4.trans.shared.b16 {%0,%1,%2,%3}, [%4];"
                 : "=r"(r[0]), "=r"(r[1]), "=r"(r[2]), "=r"(r[3]) : "r"(a));
}
__device__ __forceinline__ void mma_bf16(float* d, const uint32_t* a, uint32_t b0, uint32_t b1) {
    asm volatile("mma.sync.aligned.m16n8k16.row.col.f32.bf16.bf16.f32 "
                 "{%0,%1,%2,%3}, {%4,%5,%6,%7}, {%8,%9}, {%0,%1,%2,%3};"
                 : "+f"(d[0]), "+f"(d[1]), "+f"(d[2]), "+f"(d[3])
                 : "r"(a[0]), "r"(a[1]), "r"(a[2]), "r"(a[3]), "r"(b0), "r"(b1));
}
__device__ __forceinline__ void split2(float a, float b, uint32_t& hi, uint32_t& lo) {
    __nv_bfloat16 ah = __float2bfloat16(a);
    __nv_bfloat16 bh = __float2bfloat16(b);
    float ar = a - __bfloat162float(ah);
    float br = b - __bfloat162float(bh);
    __nv_bfloat162 H; H.x = ah; H.y = bh;
    __nv_bfloat162 L; L.x = __float2bfloat16(ar); L.y = __float2bfloat16(br);
    hi = *reinterpret_cast<uint32_t*>(&H);
    lo = *reinterpret_cast<uint32_t*>(&L);
}
__device__ __forceinline__ void load_regs4(const float* __restrict__ g, float4* r, int tid) {
    #pragma unroll
    for (int i = 0; i < 4; ++i)
        r[i] = reinterpret_cast<const float4*>(g)[tid + i * NTH];
}
__device__ __forceinline__ void store_split4(const float4* r, char* hi, char* lo, int tid) {
    #pragma unroll
    for (int i = 0; i < 4; ++i) {
        int idx = tid + i * NTH;
        float4 t = r[i];
        uint32_t h01, l01, h23, l23;
        split2(t.x, t.y, h01, l01);
        split2(t.z, t.w, h23, l23);
        int rr = idx >> 4;
        int c8 = (idx & 15) << 3;
        *reinterpret_cast<uint2*>(hi + rr * STRIDE + c8) = make_uint2(h01, h23);
        *reinterpret_cast<uint2*>(lo + rr * STRIDE + c8) = make_uint2(l01, l23);
    }
}

__global__ __launch_bounds__(NTH, 2)
void attn_mma_kernel(const float* __restrict__ qg,
                     const float* __restrict__ kg,
                     const float* __restrict__ vg,
                     const int* __restrict__ diag,
                     const int* __restrict__ maskb,
                     float* __restrict__ outp,
                     float* __restrict__ attn)
{
    extern __shared__ __align__(16) char smem[];
    const int tid  = threadIdx.x;
    const int wid  = tid >> 5;
    const int lane = tid & 31;
    const int qt   = lane & 3;
    const int b    = blockIdx.y;
    const int q0   = blockIdx.x * TQ;

    const uint32_t sb = smem_u32(smem);
    const float* kbase = kg + (size_t)b * LLEN * DD;
    const float* vbase = vg + (size_t)b * LLEN * DD;

    const int r0l = wid * 16 + (lane >> 2);          // this thread's row0 (row1 = +8)
    const size_t g0 = (size_t)b * LLEN + q0 + r0l;
    const int* m0p = maskb + g0 * LLEN;
    const int* m1p = m0p + (size_t)8 * LLEN;
    const int* d0p = diag + g0 * LLEN;
    const int* d1p = d0p + (size_t)8 * LLEN;
    float* a0p = attn + g0 * LLEN;
    float* a1p = a0p + (size_t)8 * LLEN;

    // ---- Q fragments loaded straight from global into registers (scaled 1/8) ----
    uint32_t qfh[16], qfl[16];
    {
        const float* q0p = qg + g0 * DD;
        const float* q1p = q0p + 8 * DD;
        #pragma unroll
        for (int kc = 0; kc < 4; ++kc) {
            const int c = kc * 16 + qt * 2;
            float2 x0 = *reinterpret_cast<const float2*>(q0p + c);
            float2 x1 = *reinterpret_cast<const float2*>(q1p + c);
            float2 x2 = *reinterpret_cast<const float2*>(q0p + c + 8);
            float2 x3 = *reinterpret_cast<const float2*>(q1p + c + 8);
            split2(x0.x * 0.125f, x0.y * 0.125f, qfh[4 * kc + 0], qfl[4 * kc + 0]);
            split2(x1.x * 0.125f, x1.y * 0.125f, qfh[4 * kc + 1], qfl[4 * kc + 1]);
            split2(x2.x * 0.125f, x2.y * 0.125f, qfh[4 * kc + 2], qfl[4 * kc + 2]);
            split2(x3.x * 0.125f, x3.y * 0.125f, qfh[4 * kc + 3], qfl[4 * kc + 3]);
        }
    }

    // ldmatrix per-lane address components (relative to buffer base)
    const uint32_t boff = (uint32_t)(((((lane >> 4) & 1) * 8) + (lane & 7)) * STRIDE
                                     + ((lane >> 3) & 1) * 16);
    const uint32_t voff = (uint32_t)(((((lane >> 3) & 1) * 8) + (lane & 7)) * STRIDE
                                     + ((lane >> 4) & 1) * 16);

    // preload K tile 0 and V tile 0 (separate regions, both buffer 0)
    {
        float4 r[4];
        load_regs4(kbase, r, tid);
        store_split4(r, smem + OFF_K, smem + OFF_K + BUFB, tid);
        float4 s[4];
        load_regs4(vbase, s, tid);
        store_split4(s, smem + OFF_V, smem + OFF_V + BUFB, tid);
    }

    float m0 = -3.0e38f, m1 = -3.0e38f, l0 = 0.0f, l1 = 0.0f;

    // ============ PASS 1: per-16col slices: prefetch masks -> MMA -> epilogue ============
    for (int kt = 0; kt < 32; ++kt) {
        const int k0 = kt * 64;
        float4 knext[4];
        if (kt + 1 < 32)
            load_regs4(kbase + (size_t)(k0 + 64) * DD, knext, tid);
        __syncthreads();                 // buf[kt&1] visible; prior readers done

        const int pb = kt & 1;
        const uint32_t kh_a = sb + OFF_K + pb * TILEB + boff;
        const uint32_t kl_a = kh_a + BUFB;

        // mask slice double buffers: [buf][row][j]
        int2 Mb[2][2][2], Db[2][2][2];
        #pragma unroll
        for (int j = 0; j < 2; ++j) {
            const int cb = k0 + j * 8 + qt * 2;
            Mb[0][0][j] = __ldcs(reinterpret_cast<const int2*>(m0p + cb));
            Db[0][0][j] = __ldcs(reinterpret_cast<const int2*>(d0p + cb));
            Mb[0][1][j] = __ldcs(reinterpret_cast<const int2*>(m1p + cb));
            Db[0][1][j] = __ldcs(reinterpret_cast<const int2*>(d1p + cb));
        }

        #pragma unroll
        for (int p = 0; p < 4; ++p) {
            const int cur = p & 1;
            // prefetch next slice's masks (latency hidden under this slice's MMAs)
            if (p < 3) {
                #pragma unroll
                for (int j = 0; j < 2; ++j) {
                    const int cb = k0 + (2 * (p + 1) + j) * 8 + qt * 2;
                    Mb[cur ^ 1][0][j] = __ldcs(reinterpret_cast<const int2*>(m0p + cb));
                    Db[cur ^ 1][0][j] = __ldcs(reinterpret_cast<const int2*>(d0p + cb));
                    Mb[cur ^ 1][1][j] = __ldcs(reinterpret_cast<const int2*>(m1p + cb));
                    Db[cur ^ 1][1][j] = __ldcs(reinterpret_cast<const int2*>(d1p + cb));
                }
            }

            // MMA slice p: 16 S-columns (n-tiles 2p, 2p+1)
            float acc[2][4];
            #pragma unroll
            for (int j = 0; j < 2; ++j)
                #pragma unroll
                for (int i = 0; i < 4; ++i) acc[j][i] = 0.0f;
            #pragma unroll
            for (int kc = 0; kc < 4; ++kc) {
                uint32_t kh4[4], kl4[4];
                ldsm4(kh_a + p * 16 * STRIDE + kc * 32, kh4);
                ldsm4(kl_a + p * 16 * STRIDE + kc * 32, kl4);
                mma_bf16(acc[0], qfh + 4 * kc, kh4[0], kh4[1]);
                mma_bf16(acc[0], qfh + 4 * kc, kl4[0], kl4[1]);
                mma_bf16(acc[0], qfl + 4 * kc, kh4[0], kh4[1]);
                mma_bf16(acc[1], qfh + 4 * kc, kh4[2], kh4[3]);
                mma_bf16(acc[1], qfh + 4 * kc, kl4[2], kl4[3]);
                mma_bf16(acc[1], qfl + 4 * kc, kh4[2], kh4[3]);
            }

            // epilogue slice p: masks + score stores + per-slice online stats
            float smax0 = -3.0e38f, smax1 = -3.0e38f;
            #pragma unroll
            for (int j = 0; j < 2; ++j) {
                const int cb = k0 + (2 * p + j) * 8 + qt * 2;
                float s0 = acc[j][0], s1 = acc[j][1];
                float s2 = acc[j][2], s3 = acc[j][3];
                if (Mb[cur][0][j].x)      s0 = NEG_INF;
                if (Db[cur][0][j].x == 0) s0 = -1.0e32f;
                if (Mb[cur][0][j].y)      s1 = NEG_INF;
                if (Db[cur][0][j].y == 0) s1 = -1.0e32f;
                if (Mb[cur][1][j].x)      s2 = NEG_INF;
                if (Db[cur][1][j].x == 0) s2 = -1.0e32f;
                if (Mb[cur][1][j].y)      s3 = NEG_INF;
                if (Db[cur][1][j].y == 0) s3 = -1.0e32f;
                __stcs(reinterpret_cast<float2*>(a0p + cb), make_float2(s0, s1));
                __stcs(reinterpret_cast<float2*>(a1p + cb), make_float2(s2, s3));
                acc[j][0] = s0; acc[j][1] = s1; acc[j][2] = s2; acc[j][3] = s3;
                smax0 = fmaxf(smax0, fmaxf(s0, s1));
                smax1 = fmaxf(smax1, fmaxf(s2, s3));
            }
            smax0 = fmaxf(smax0, __shfl_xor_sync(0xffffffffu, smax0, 1));
            smax0 = fmaxf(smax0, __shfl_xor_sync(0xffffffffu, smax0, 2));
            smax1 = fmaxf(smax1, __shfl_xor_sync(0xffffffffu, smax1, 1));
            smax1 = fmaxf(smax1, __shfl_xor_sync(0xffffffffu, smax1, 2));
            const float mn0 = fmaxf(m0, smax0);
            const float mn1 = fmaxf(m1, smax1);
            float e0 = __expf(acc[0][0] - mn0) + __expf(acc[0][1] - mn0)
                     + __expf(acc[1][0] - mn0) + __expf(acc[1][1] - mn0);
            float e1 = __expf(acc[0][2] - mn1) + __expf(acc[0][3] - mn1)
                     + __expf(acc[1][2] - mn1) + __expf(acc[1][3] - mn1);
            e0 += __shfl_xor_sync(0xffffffffu, e0, 1);
            e0 += __shfl_xor_sync(0xffffffffu, e0, 2);
            e1 += __shfl_xor_sync(0xffffffffu, e1, 1);
            e1 += __shfl_xor_sync(0xffffffffu, e1, 2);
            l0 = l0 * __expf(m0 - mn0) + e0;  m0 = mn0;
            l1 = l1 * __expf(m1 - mn1) + e1;  m1 = mn1;
        }

        if (kt + 1 < 32)
            store_split4(knext, smem + OFF_K + (pb ^ 1) * TILEB,
                         smem + OFF_K + (pb ^ 1) * TILEB + BUFB, tid);
    }

    const float rinv0 = 1.0f / l0;
    const float rinv1 = 1.0f / l1;

    float oacc[8][4];
    #pragma unroll
    for (int nt = 0; nt < 8; ++nt)
        #pragma unroll
        for (int i = 0; i < 4; ++i) oacc[nt][i] = 0.0f;

    // ============ PASS 2: per-16krow slices: prefetch scores -> exp/probs -> PV ============
    for (int kt = 0; kt < 32; ++kt) {
        const int k0 = kt * 64;
        float4 vnext[4];
        if (kt + 1 < 32)
            load_regs4(vbase + (size_t)(k0 + 64) * DD, vnext, tid);

        // score slice double buffer: [buf][4] float2 = rows{0,1} x cols{+0,+8}
        float2 Sb[2][4];
        {
            const int cA = k0 + qt * 2;
            Sb[0][0] = __ldcs(reinterpret_cast<const float2*>(a0p + cA));
            Sb[0][1] = __ldcs(reinterpret_cast<const float2*>(a0p + cA + 8));
            Sb[0][2] = __ldcs(reinterpret_cast<const float2*>(a1p + cA));
            Sb[0][3] = __ldcs(reinterpret_cast<const float2*>(a1p + cA + 8));
        }
        __syncthreads();                 // V buf[kt&1] visible; prior readers done

        const int pb = kt & 1;
        const uint32_t vh_a = sb + OFF_V + pb * TILEB + voff;
        const uint32_t vl_a = vh_a + BUFB;

        #pragma unroll
        for (int kc2 = 0; kc2 < 4; ++kc2) {
            const int cur = kc2 & 1;
            if (kc2 < 3) {
                const int cA = k0 + (kc2 + 1) * 16 + qt * 2;
                Sb[cur ^ 1][0] = __ldcs(reinterpret_cast<const float2*>(a0p + cA));
                Sb[cur ^ 1][1] = __ldcs(reinterpret_cast<const float2*>(a0p + cA + 8));
                Sb[cur ^ 1][2] = __ldcs(reinterpret_cast<const float2*>(a1p + cA));
                Sb[cur ^ 1][3] = __ldcs(reinterpret_cast<const float2*>(a1p + cA + 8));
            }

            // exp + prob stores + P fragments for this 16-k slice
            const int cA = k0 + kc2 * 16 + qt * 2;
            float p00 = __expf(Sb[cur][0].x - m0) * rinv0;
            float p01 = __expf(Sb[cur][0].y - m0) * rinv0;
            float p02 = __expf(Sb[cur][1].x - m0) * rinv0;
            float p03 = __expf(Sb[cur][1].y - m0) * rinv0;
            float p10 = __expf(Sb[cur][2].x - m1) * rinv1;
            float p11 = __expf(Sb[cur][2].y - m1) * rinv1;
            float p12 = __expf(Sb[cur][3].x - m1) * rinv1;
            float p13 = __expf(Sb[cur][3].y - m1) * rinv1;
            __stcs(reinterpret_cast<float2*>(a0p + cA),     make_float2(p00, p01));
            __stcs(reinterpret_cast<float2*>(a0p + cA + 8), make_float2(p02, p03));
            __stcs(reinterpret_cast<float2*>(a1p + cA),     make_float2(p10, p11));
            __stcs(reinterpret_cast<float2*>(a1p + cA + 8), make_float2(p12, p13));
            uint32_t ph[4], pl[4];
            split2(p00, p01, ph[0], pl[0]);   // row0, k-lo
            split2(p10, p11, ph[1], pl[1]);   // row1, k-lo
            split2(p02, p03, ph[2], pl[2]);   // row0, k-hi
            split2(p12, p13, ph[3], pl[3]);   // row1, k-hi

            #pragma unroll
            for (int p = 0; p < 4; ++p) {
                uint32_t vh4[4], vl4[4];
                ldsm4t(vh_a + kc2 * 16 * STRIDE + p * 32, vh4);
                ldsm4t(vl_a + kc2 * 16 * STRIDE + p * 32, vl4);
                mma_bf16(oacc[2 * p],     ph, vh4[0], vh4[1]);
                mma_bf16(oacc[2 * p],     ph, vl4[0], vl4[1]);
                mma_bf16(oacc[2 * p],     pl, vh4[0], vh4[1]);
                mma_bf16(oacc[2 * p + 1], ph, vh4[2], vh4[3]);
                mma_bf16(oacc[2 * p + 1], ph, vl4[2], vl4[3]);
                mma_bf16(oacc[2 * p + 1], pl, vh4[2], vh4[3]);
            }
        }
        if (kt + 1 < 32)
            store_split4(vnext, smem + OFF_V + (pb ^ 1) * TILEB,
                         smem + OFF_V + (pb ^ 1) * TILEB + BUFB, tid);
    }

    // ---- write output ----
    float* o0 = outp + g0 * DD;
    float* o1 = o0 + (size_t)8 * DD;
    #pragma unroll
    for (int nt = 0; nt < 8; ++nt) {
        const int cb = nt * 8 + qt * 2;
        __stcs(reinterpret_cast<float2*>(o0 + cb), make_float2(oacc[nt][0], oacc[nt][1]));
        __stcs(reinterpret_cast<float2*>(o1 + cb), make_float2(oacc[nt][2], oacc[nt][3]));
    }
}

extern "C" void kernel_launch(void* const* d_in, const int* in_sizes, int n_in,
                              void* d_out, int out_size)
{
    const float* q    = (const float*)d_in[0];
    const float* k    = (const float*)d_in[1];
    const float* v    = (const float*)d_in[2];
    const int*   diag = (const int*)d_in[3];
    const int*   mask = (const int*)d_in[4];

    float* out  = (float*)d_out;                     // [B, L, D]
    float* attn = out + (size_t)BB * LLEN * DD;      // [B, L, L]

    cudaFuncSetAttribute(attn_mma_kernel,
                         cudaFuncAttributeMaxDynamicSharedMemorySize, SMEM_TOTAL);
    dim3 grid(LLEN / TQ, BB);
    attn_mma_kernel<<<grid, NTH, SMEM_TOTAL>>>(q, k, v, diag, mask, out, attn);
}

// round 10
// speedup vs baseline: 1.8031x; 1.0976x over previous
#include <cuda_runtime.h>
#include <cuda_bf16.h>
#include <cuda_fp16.h>
#include <stdint.h>

#define BB 16
#define LLEN 2048
#define DD 64
#define TQ 128
#define NTH 256
#define STRIDE 144                  // smem row stride bytes (72 bf16, conflict-free)
#define BUFB (64 * STRIDE)          // one 64-row half (hi or lo) = 9216 B
#define TILEB (2 * BUFB)            // hi+lo buffer = 18432 B

#define OFF_V 0                     // region A: V double buffer (pass 2)
#define OFF_K (2 * TILEB)           // region B: K double buffer (pass 1)
#define SMEM_TOTAL (4 * TILEB)      // 73728 B

#define NEG_INF __int_as_float(0xff800000)
#define NROWSG (BB * LLEN)          // 32768 global q-rows

// fp16 unnormalized probs h = exp(s - M_slice): [row][col/2] half2 (134 MB)
__device__ __half2 g_h[(size_t)NROWSG * (LLEN / 2)];
// per-(slice,row) running max at write time: [slice][row] (16 MB)
__device__ float g_M[(size_t)128 * NROWSG];

// ---------------- helpers ----------------
__device__ __forceinline__ uint32_t smem_u32(const void* p) {
    uint32_t a;
    asm("{ .reg .u64 t; cvta.to.shared.u64 t, %1; cvt.u32.u64 %0, t; }" : "=r"(a) : "l"(p));
    return a;
}
__device__ __forceinline__ void ldsm4(uint32_t a, uint32_t r[4]) {
    asm volatile("ldmatrix.sync.aligned.m8n8.x4.shared.b16 {%0,%1,%2,%3}, [%4];"
                 : "=r"(r[0]), "=r"(r[1]), "=r"(r[2]), "=r"(r[3]) : "r"(a));
}
__device__ __forceinline__ void ldsm4t(uint32_t a, uint32_t r[4]) {
    asm volatile("ldmatrix.sync.aligned.m8n8.x4.trans.shared.b16 {%0,%1,%2,%3}, [%4];"
                 : "=r"(r[0]), "=r"(r[1]), "=r"(r[2]), "=r"(r[3]) : "r"(a));
}
__device__ __forceinline__ void mma_bf16(float* d, const uint32_t* a, uint32_t b0, uint32_t b1) {
    asm volatile("mma.sync.aligned.m16n8k16.row.col.f32.bf16.bf16.f32 "
                 "{%0,%1,%2,%3}, {%4,%5,%6,%7}, {%8,%9}, {%0,%1,%2,%3};"
                 : "+f"(d[0]), "+f"(d[1]), "+f"(d[2]), "+f"(d[3])
                 : "r"(a[0]), "r"(a[1]), "r"(a[2]), "r"(a[3]), "r"(b0), "r"(b1));
}
__device__ __forceinline__ void split2(float a, float b, uint32_t& hi, uint32_t& lo) {
    __nv_bfloat16 ah = __float2bfloat16(a);
    __nv_bfloat16 bh = __float2bfloat16(b);
    float ar = a - __bfloat162float(ah);
    float br = b - __bfloat162float(bh);
    __nv_bfloat162 H; H.x = ah; H.y = bh;
    __nv_bfloat162 L; L.x = __float2bfloat16(ar); L.y = __float2bfloat16(br);
    hi = *reinterpret_cast<uint32_t*>(&H);
    lo = *reinterpret_cast<uint32_t*>(&L);
}
__device__ __forceinline__ void load_regs4(const float* __restrict__ g, float4* r, int tid) {
    #pragma unroll
    for (int i = 0; i < 4; ++i)
        r[i] = reinterpret_cast<const float4*>(g)[tid + i * NTH];
}
__device__ __forceinline__ void store_split4(const float4* r, char* hi, char* lo, int tid) {
    #pragma unroll
    for (int i = 0; i < 4; ++i) {
        int idx = tid + i * NTH;
        float4 t = r[i];
        uint32_t h01, l01, h23, l23;
        split2(t.x, t.y, h01, l01);
        split2(t.z, t.w, h23, l23);
        int rr = idx >> 4;
        int c8 = (idx & 15) << 3;
        *reinterpret_cast<uint2*>(hi + rr * STRIDE + c8) = make_uint2(h01, h23);
        *reinterpret_cast<uint2*>(lo + rr * STRIDE + c8) = make_uint2(l01, l23);
    }
}

__global__ __launch_bounds__(NTH, 2)
void attn_mma_kernel(const float* __restrict__ qg,
                     const float* __restrict__ kg,
                     const float* __restrict__ vg,
                     const int* __restrict__ diag,
                     const int* __restrict__ maskb,
                     float* __restrict__ outp,
                     float* __restrict__ attn)
{
    extern __shared__ __align__(16) char smem[];
    const int tid  = threadIdx.x;
    const int wid  = tid >> 5;
    const int lane = tid & 31;
    const int qt   = lane & 3;
    const int b    = blockIdx.y;
    const int q0   = blockIdx.x * TQ;

    const uint32_t sb = smem_u32(smem);
    const float* kbase = kg + (size_t)b * LLEN * DD;
    const float* vbase = vg + (size_t)b * LLEN * DD;

    const int r0l = wid * 16 + (lane >> 2);          // this thread's row0 (row1 = +8)
    const size_t g0 = (size_t)b * LLEN + q0 + r0l;
    const int* m0p = maskb + g0 * LLEN;
    const int* m1p = m0p + (size_t)8 * LLEN;
    const int* d0p = diag + g0 * LLEN;
    const int* d1p = d0p + (size_t)8 * LLEN;
    float* a0p = attn + g0 * LLEN;
    float* a1p = a0p + (size_t)8 * LLEN;
    __half2* h0p = g_h + g0 * (LLEN / 2);
    __half2* h1p = h0p + (size_t)8 * (LLEN / 2);

    // ---- Q fragments loaded straight from global into registers (scaled 1/8) ----
    uint32_t qfh[16], qfl[16];
    {
        const float* q0p = qg + g0 * DD;
        const float* q1p = q0p + 8 * DD;
        #pragma unroll
        for (int kc = 0; kc < 4; ++kc) {
            const int c = kc * 16 + qt * 2;
            float2 x0 = *reinterpret_cast<const float2*>(q0p + c);
            float2 x1 = *reinterpret_cast<const float2*>(q1p + c);
            float2 x2 = *reinterpret_cast<const float2*>(q0p + c + 8);
            float2 x3 = *reinterpret_cast<const float2*>(q1p + c + 8);
            split2(x0.x * 0.125f, x0.y * 0.125f, qfh[4 * kc + 0], qfl[4 * kc + 0]);
            split2(x1.x * 0.125f, x1.y * 0.125f, qfh[4 * kc + 1], qfl[4 * kc + 1]);
            split2(x2.x * 0.125f, x2.y * 0.125f, qfh[4 * kc + 2], qfl[4 * kc + 2]);
            split2(x3.x * 0.125f, x3.y * 0.125f, qfh[4 * kc + 3], qfl[4 * kc + 3]);
        }
    }

    // ldmatrix per-lane address components (relative to buffer base)
    const uint32_t boff = (uint32_t)(((((lane >> 4) & 1) * 8) + (lane & 7)) * STRIDE
                                     + ((lane >> 3) & 1) * 16);
    const uint32_t voff = (uint32_t)(((((lane >> 3) & 1) * 8) + (lane & 7)) * STRIDE
                                     + ((lane >> 4) & 1) * 16);

    // preload K tile 0 and V tile 0 (separate regions, both buffer 0)
    {
        float4 r[4];
        load_regs4(kbase, r, tid);
        store_split4(r, smem + OFF_K, smem + OFF_K + BUFB, tid);
        float4 s[4];
        load_regs4(vbase, s, tid);
        store_split4(s, smem + OFF_V, smem + OFF_V + BUFB, tid);
    }

    float m0 = -3.0e38f, m1 = -3.0e38f, l0 = 0.0f, l1 = 0.0f;

    // ============ PASS 1: per-16col slices: masks -> MMA -> h(fp16)+M_s write + stats ============
    for (int kt = 0; kt < 32; ++kt) {
        const int k0 = kt * 64;
        float4 knext[4];
        if (kt + 1 < 32)
            load_regs4(kbase + (size_t)(k0 + 64) * DD, knext, tid);
        __syncthreads();                 // buf[kt&1] visible; prior readers done

        const int pb = kt & 1;
        const uint32_t kh_a = sb + OFF_K + pb * TILEB + boff;
        const uint32_t kl_a = kh_a + BUFB;

        // mask slice double buffers: [buf][row][j]
        int2 Mb[2][2][2], Db[2][2][2];
        #pragma unroll
        for (int j = 0; j < 2; ++j) {
            const int cb = k0 + j * 8 + qt * 2;
            Mb[0][0][j] = __ldcs(reinterpret_cast<const int2*>(m0p + cb));
            Db[0][0][j] = __ldcs(reinterpret_cast<const int2*>(d0p + cb));
            Mb[0][1][j] = __ldcs(reinterpret_cast<const int2*>(m1p + cb));
            Db[0][1][j] = __ldcs(reinterpret_cast<const int2*>(d1p + cb));
        }

        #pragma unroll
        for (int p = 0; p < 4; ++p) {
            const int cur = p & 1;
            // prefetch next slice's masks (latency hidden under this slice's MMAs)
            if (p < 3) {
                #pragma unroll
                for (int j = 0; j < 2; ++j) {
                    const int cb = k0 + (2 * (p + 1) + j) * 8 + qt * 2;
                    Mb[cur ^ 1][0][j] = __ldcs(reinterpret_cast<const int2*>(m0p + cb));
                    Db[cur ^ 1][0][j] = __ldcs(reinterpret_cast<const int2*>(d0p + cb));
                    Mb[cur ^ 1][1][j] = __ldcs(reinterpret_cast<const int2*>(m1p + cb));
                    Db[cur ^ 1][1][j] = __ldcs(reinterpret_cast<const int2*>(d1p + cb));
                }
            }

            // MMA slice p: 16 S-columns (n-tiles 2p, 2p+1)
            float acc[2][4];
            #pragma unroll
            for (int j = 0; j < 2; ++j)
                #pragma unroll
                for (int i = 0; i < 4; ++i) acc[j][i] = 0.0f;
            #pragma unroll
            for (int kc = 0; kc < 4; ++kc) {
                uint32_t kh4[4], kl4[4];
                ldsm4(kh_a + p * 16 * STRIDE + kc * 32, kh4);
                ldsm4(kl_a + p * 16 * STRIDE + kc * 32, kl4);
                mma_bf16(acc[0], qfh + 4 * kc, kh4[0], kh4[1]);
                mma_bf16(acc[0], qfh + 4 * kc, kl4[0], kl4[1]);
                mma_bf16(acc[0], qfl + 4 * kc, kh4[0], kh4[1]);
                mma_bf16(acc[1], qfh + 4 * kc, kh4[2], kh4[3]);
                mma_bf16(acc[1], qfh + 4 * kc, kl4[2], kl4[3]);
                mma_bf16(acc[1], qfl + 4 * kc, kh4[2], kh4[3]);
            }

            // epilogue slice p: masks + per-slice online stats + h(fp16)/M_s stores
            float smax0 = -3.0e38f, smax1 = -3.0e38f;
            #pragma unroll
            for (int j = 0; j < 2; ++j) {
                float s0 = acc[j][0], s1 = acc[j][1];
                float s2 = acc[j][2], s3 = acc[j][3];
                if (Mb[cur][0][j].x)      s0 = NEG_INF;
                if (Db[cur][0][j].x == 0) s0 = -1.0e32f;
                if (Mb[cur][0][j].y)      s1 = NEG_INF;
                if (Db[cur][0][j].y == 0) s1 = -1.0e32f;
                if (Mb[cur][1][j].x)      s2 = NEG_INF;
                if (Db[cur][1][j].x == 0) s2 = -1.0e32f;
                if (Mb[cur][1][j].y)      s3 = NEG_INF;
                if (Db[cur][1][j].y == 0) s3 = -1.0e32f;
                acc[j][0] = s0; acc[j][1] = s1; acc[j][2] = s2; acc[j][3] = s3;
                smax0 = fmaxf(smax0, fmaxf(s0, s1));
                smax1 = fmaxf(smax1, fmaxf(s2, s3));
            }
            smax0 = fmaxf(smax0, __shfl_xor_sync(0xffffffffu, smax0, 1));
            smax0 = fmaxf(smax0, __shfl_xor_sync(0xffffffffu, smax0, 2));
            smax1 = fmaxf(smax1, __shfl_xor_sync(0xffffffffu, smax1, 1));
            smax1 = fmaxf(smax1, __shfl_xor_sync(0xffffffffu, smax1, 2));
            const float mn0 = fmaxf(m0, smax0);
            const float mn1 = fmaxf(m1, smax1);

            // per-element exps (reused for both l-sum and fp16 h store)
            float h00 = __expf(acc[0][0] - mn0), h01 = __expf(acc[0][1] - mn0);
            float h02 = __expf(acc[1][0] - mn0), h03 = __expf(acc[1][1] - mn0);
            float h10 = __expf(acc[0][2] - mn1), h11 = __expf(acc[0][3] - mn1);
            float h12 = __expf(acc[1][2] - mn1), h13 = __expf(acc[1][3] - mn1);

            const int cb0 = k0 + (2 * p) * 8 + qt * 2;
            const int cb1 = cb0 + 8;
            __stcs(h0p + (cb0 >> 1), __floats2half2_rn(h00, h01));
            __stcs(h0p + (cb1 >> 1), __floats2half2_rn(h02, h03));
            __stcs(h1p + (cb0 >> 1), __floats2half2_rn(h10, h11));
            __stcs(h1p + (cb1 >> 1), __floats2half2_rn(h12, h13));
            if (qt == 0) {
                const size_t ms = (size_t)(kt * 4 + p) * NROWSG;
                g_M[ms + g0]     = mn0;
                g_M[ms + g0 + 8] = mn1;
            }

            float e0 = h00 + h01 + h02 + h03;
            float e1 = h10 + h11 + h12 + h13;
            e0 += __shfl_xor_sync(0xffffffffu, e0, 1);
            e0 += __shfl_xor_sync(0xffffffffu, e0, 2);
            e1 += __shfl_xor_sync(0xffffffffu, e1, 1);
            e1 += __shfl_xor_sync(0xffffffffu, e1, 2);
            l0 = l0 * __expf(m0 - mn0) + e0;  m0 = mn0;
            l1 = l1 * __expf(m1 - mn1) + e1;  m1 = mn1;
        }

        if (kt + 1 < 32)
            store_split4(knext, smem + OFF_K + (pb ^ 1) * TILEB,
                         smem + OFF_K + (pb ^ 1) * TILEB + BUFB, tid);
    }

    const float rinv0 = 1.0f / l0;
    const float rinv1 = 1.0f / l1;

    float oacc[8][4];
    #pragma unroll
    for (int nt = 0; nt < 8; ++nt)
        #pragma unroll
        for (int i = 0; i < 4; ++i) oacc[nt][i] = 0.0f;

    // ============ PASS 2: read h(fp16)+M_s -> probs write -> PV ============
    for (int kt = 0; kt < 32; ++kt) {
        const int k0 = kt * 64;
        float4 vnext[4];
        if (kt + 1 < 32)
            load_regs4(vbase + (size_t)(k0 + 64) * DD, vnext, tid);

        // h slice double buffer: [buf][4] half2-as-u32 = rows{0,1} x cols{+0,+8}; M_s per row
        uint32_t Hb[2][4];
        float Mb0[2], Mb1[2];
        {
            const int cA = k0 + qt * 2;
            Hb[0][0] = __ldcs(reinterpret_cast<const uint32_t*>(h0p + (cA >> 1)));
            Hb[0][1] = __ldcs(reinterpret_cast<const uint32_t*>(h0p + ((cA + 8) >> 1)));
            Hb[0][2] = __ldcs(reinterpret_cast<const uint32_t*>(h1p + (cA >> 1)));
            Hb[0][3] = __ldcs(reinterpret_cast<const uint32_t*>(h1p + ((cA + 8) >> 1)));
            const size_t ms = (size_t)(kt * 4) * NROWSG;
            Mb0[0] = __ldcs(&g_M[ms + g0]);
            Mb1[0] = __ldcs(&g_M[ms + g0 + 8]);
        }
        __syncthreads();                 // V buf[kt&1] visible; prior readers done

        const int pb = kt & 1;
        const uint32_t vh_a = sb + OFF_V + pb * TILEB + voff;
        const uint32_t vl_a = vh_a + BUFB;

        #pragma unroll
        for (int kc2 = 0; kc2 < 4; ++kc2) {
            const int cur = kc2 & 1;
            if (kc2 < 3) {
                const int cA = k0 + (kc2 + 1) * 16 + qt * 2;
                Hb[cur ^ 1][0] = __ldcs(reinterpret_cast<const uint32_t*>(h0p + (cA >> 1)));
                Hb[cur ^ 1][1] = __ldcs(reinterpret_cast<const uint32_t*>(h0p + ((cA + 8) >> 1)));
                Hb[cur ^ 1][2] = __ldcs(reinterpret_cast<const uint32_t*>(h1p + (cA >> 1)));
                Hb[cur ^ 1][3] = __ldcs(reinterpret_cast<const uint32_t*>(h1p + ((cA + 8) >> 1)));
                const size_t ms = (size_t)(kt * 4 + kc2 + 1) * NROWSG;
                Mb0[cur ^ 1] = __ldcs(&g_M[ms + g0]);
                Mb1[cur ^ 1] = __ldcs(&g_M[ms + g0 + 8]);
            }

            // per-slice normalization factors (exact flash identity)
            const float f0 = __expf(Mb0[cur] - m0) * rinv0;
            const float f1 = __expf(Mb1[cur] - m1) * rinv1;

            const int cA = k0 + kc2 * 16 + qt * 2;
            float2 xa = __half22float2(*reinterpret_cast<const __half2*>(&Hb[cur][0]));
            float2 xb = __half22float2(*reinterpret_cast<const __half2*>(&Hb[cur][1]));
            float2 xc = __half22float2(*reinterpret_cast<const __half2*>(&Hb[cur][2]));
            float2 xd = __half22float2(*reinterpret_cast<const __half2*>(&Hb[cur][3]));
            float p00 = xa.x * f0, p01 = xa.y * f0;
            float p02 = xb.x * f0, p03 = xb.y * f0;
            float p10 = xc.x * f1, p11 = xc.y * f1;
            float p12 = xd.x * f1, p13 = xd.y * f1;
            __stcs(reinterpret_cast<float2*>(a0p + cA),     make_float2(p00, p01));
            __stcs(reinterpret_cast<float2*>(a0p + cA + 8), make_float2(p02, p03));
            __stcs(reinterpret_cast<float2*>(a1p + cA),     make_float2(p10, p11));
            __stcs(reinterpret_cast<float2*>(a1p + cA + 8), make_float2(p12, p13));
            uint32_t ph[4], pl[4];
            split2(p00, p01, ph[0], pl[0]);   // row0, k-lo
            split2(p10, p11, ph[1], pl[1]);   // row1, k-lo
            split2(p02, p03, ph[2], pl[2]);   // row0, k-hi
            split2(p12, p13, ph[3], pl[3]);   // row1, k-hi

            #pragma unroll
            for (int p = 0; p < 4; ++p) {
                uint32_t vh4[4], vl4[4];
                ldsm4t(vh_a + kc2 * 16 * STRIDE + p * 32, vh4);
                ldsm4t(vl_a + kc2 * 16 * STRIDE + p * 32, vl4);
                mma_bf16(oacc[2 * p],     ph, vh4[0], vh4[1]);
                mma_bf16(oacc[2 * p],     ph, vl4[0], vl4[1]);
                mma_bf16(oacc[2 * p],     pl, vh4[0], vh4[1]);
                mma_bf16(oacc[2 * p + 1], ph, vh4[2], vh4[3]);
                mma_bf16(oacc[2 * p + 1], ph, vl4[2], vl4[3]);
                mma_bf16(oacc[2 * p + 1], pl, vh4[2], vh4[3]);
            }
        }
        if (kt + 1 < 32)
            store_split4(vnext, smem + OFF_V + (pb ^ 1) * TILEB,
                         smem + OFF_V + (pb ^ 1) * TILEB + BUFB, tid);
    }

    // ---- write output ----
    float* o0 = outp + g0 * DD;
    float* o1 = o0 + (size_t)8 * DD;
    #pragma unroll
    for (int nt = 0; nt < 8; ++nt) {
        const int cb = nt * 8 + qt * 2;
        __stcs(reinterpret_cast<float2*>(o0 + cb), make_float2(oacc[nt][0], oacc[nt][1]));
        __stcs(reinterpret_cast<float2*>(o1 + cb), make_float2(oacc[nt][2], oacc[nt][3]));
    }
}

extern "C" void kernel_launch(void* const* d_in, const int* in_sizes, int n_in,
                              void* d_out, int out_size)
{
    const float* q    = (const float*)d_in[0];
    const float* k    = (const float*)d_in[1];
    const float* v    = (const float*)d_in[2];
    const int*   diag = (const int*)d_in[3];
    const int*   mask = (const int*)d_in[4];

    float* out  = (float*)d_out;                     // [B, L, D]
    float* attn = out + (size_t)BB * LLEN * DD;      // [B, L, L]

    cudaFuncSetAttribute(attn_mma_kernel,
                         cudaFuncAttributeMaxDynamicSharedMemorySize, SMEM_TOTAL);
    dim3 grid(LLEN / TQ, BB);
    attn_mma_kernel<<<grid, NTH, SMEM_TOTAL>>>(q, k, v, diag, mask, out, attn);
}

// round 11
// speedup vs baseline: 1.9613x; 1.0877x over previous
#include <cuda_runtime.h>
#include <cuda_bf16.h>
#include <cuda_fp16.h>
#include <stdint.h>

#define BB 16
#define LLEN 2048
#define DD 64
#define TQ 128
#define NTH 256
#define STRIDE 144                  // smem row stride bytes (conflict-free)
#define BUFB (64 * STRIDE)          // one 64-row half tile = 9216 B
#define TILEB (2 * BUFB)            // K hi+lo buffer = 18432 B

#define OFF_V 0                     // V double buffer (fp16, single tile each) = 2*9216
#define OFF_K (2 * BUFB)            // K double buffer (bf16 hi+lo) = 2*18432
#define SMEM_TOTAL (OFF_K + 2 * TILEB)   // 55296 B

#define NEG_INF __int_as_float(0xff800000)
#define NROWSG (BB * LLEN)          // 32768 global q-rows

// fp16 unnormalized probs h = exp(s - M_slice): [row][col/2] half2 (134 MB)
__device__ __half2 g_h[(size_t)NROWSG * (LLEN / 2)];
// per-(slice,row) running max at write time: [slice][row] (16 MB)
__device__ float g_M[(size_t)128 * NROWSG];

// ---------------- helpers ----------------
__device__ __forceinline__ uint32_t smem_u32(const void* p) {
    uint32_t a;
    asm("{ .reg .u64 t; cvta.to.shared.u64 t, %1; cvt.u32.u64 %0, t; }" : "=r"(a) : "l"(p));
    return a;
}
__device__ __forceinline__ void ldsm4(uint32_t a, uint32_t r[4]) {
    asm volatile("ldmatrix.sync.aligned.m8n8.x4.shared.b16 {%0,%1,%2,%3}, [%4];"
                 : "=r"(r[0]), "=r"(r[1]), "=r"(r[2]), "=r"(r[3]) : "r"(a));
}
__device__ __forceinline__ void ldsm4t(uint32_t a, uint32_t r[4]) {
    asm volatile("ldmatrix.sync.aligned.m8n8.x4.trans.shared.b16 {%0,%1,%2,%3}, [%4];"
                 : "=r"(r[0]), "=r"(r[1]), "=r"(r[2]), "=r"(r[3]) : "r"(a));
}
__device__ __forceinline__ void mma_bf16(float* d, const uint32_t* a, uint32_t b0, uint32_t b1) {
    asm volatile("mma.sync.aligned.m16n8k16.row.col.f32.bf16.bf16.f32 "
                 "{%0,%1,%2,%3}, {%4,%5,%6,%7}, {%8,%9}, {%0,%1,%2,%3};"
                 : "+f"(d[0]), "+f"(d[1]), "+f"(d[2]), "+f"(d[3])
                 : "r"(a[0]), "r"(a[1]), "r"(a[2]), "r"(a[3]), "r"(b0), "r"(b1));
}
__device__ __forceinline__ void mma_f16(float* d, const uint32_t* a, uint32_t b0, uint32_t b1) {
    asm volatile("mma.sync.aligned.m16n8k16.row.col.f32.f16.f16.f32 "
                 "{%0,%1,%2,%3}, {%4,%5,%6,%7}, {%8,%9}, {%0,%1,%2,%3};"
                 : "+f"(d[0]), "+f"(d[1]), "+f"(d[2]), "+f"(d[3])
                 : "r"(a[0]), "r"(a[1]), "r"(a[2]), "r"(a[3]), "r"(b0), "r"(b1));
}
__device__ __forceinline__ void split2(float a, float b, uint32_t& hi, uint32_t& lo) {
    __nv_bfloat16 ah = __float2bfloat16(a);
    __nv_bfloat16 bh = __float2bfloat16(b);
    float ar = a - __bfloat162float(ah);
    float br = b - __bfloat162float(bh);
    __nv_bfloat162 H; H.x = ah; H.y = bh;
    __nv_bfloat162 L; L.x = __float2bfloat16(ar); L.y = __float2bfloat16(br);
    hi = *reinterpret_cast<uint32_t*>(&H);
    lo = *reinterpret_cast<uint32_t*>(&L);
}
__device__ __forceinline__ uint32_t pack_h2(float a, float b) {
    __half2 h = __floats2half2_rn(a, b);
    return *reinterpret_cast<uint32_t*>(&h);
}
__device__ __forceinline__ void load_regs4(const float* __restrict__ g, float4* r, int tid) {
    #pragma unroll
    for (int i = 0; i < 4; ++i)
        r[i] = reinterpret_cast<const float4*>(g)[tid + i * NTH];
}
// K: fp32 -> bf16 hi/lo tiles
__device__ __forceinline__ void store_split4(const float4* r, char* hi, char* lo, int tid) {
    #pragma unroll
    for (int i = 0; i < 4; ++i) {
        int idx = tid + i * NTH;
        float4 t = r[i];
        uint32_t h01, l01, h23, l23;
        split2(t.x, t.y, h01, l01);
        split2(t.z, t.w, h23, l23);
        int rr = idx >> 4;
        int c8 = (idx & 15) << 3;
        *reinterpret_cast<uint2*>(hi + rr * STRIDE + c8) = make_uint2(h01, h23);
        *reinterpret_cast<uint2*>(lo + rr * STRIDE + c8) = make_uint2(l01, l23);
    }
}
// V: fp32 -> fp16 single tile
__device__ __forceinline__ void store_half4(const float4* r, char* dst, int tid) {
    #pragma unroll
    for (int i = 0; i < 4; ++i) {
        int idx = tid + i * NTH;
        float4 t = r[i];
        uint32_t a = pack_h2(t.x, t.y);
        uint32_t b = pack_h2(t.z, t.w);
        int rr = idx >> 4;
        int c8 = (idx & 15) << 3;
        *reinterpret_cast<uint2*>(dst + rr * STRIDE + c8) = make_uint2(a, b);
    }
}

__global__ __launch_bounds__(NTH, 2)
void attn_mma_kernel(const float* __restrict__ qg,
                     const float* __restrict__ kg,
                     const float* __restrict__ vg,
                     const int* __restrict__ diag,
                     const int* __restrict__ maskb,
                     float* __restrict__ outp,
                     float* __restrict__ attn)
{
    extern __shared__ __align__(16) char smem[];
    const int tid  = threadIdx.x;
    const int wid  = tid >> 5;
    const int lane = tid & 31;
    const int qt   = lane & 3;
    const int b    = blockIdx.y;
    const int q0   = blockIdx.x * TQ;

    const uint32_t sb = smem_u32(smem);
    const float* kbase = kg + (size_t)b * LLEN * DD;
    const float* vbase = vg + (size_t)b * LLEN * DD;

    const int r0l = wid * 16 + (lane >> 2);          // this thread's row0 (row1 = +8)
    const size_t g0 = (size_t)b * LLEN + q0 + r0l;
    const int* m0p = maskb + g0 * LLEN;
    const int* m1p = m0p + (size_t)8 * LLEN;
    const int* d0p = diag + g0 * LLEN;
    const int* d1p = d0p + (size_t)8 * LLEN;
    float* a0p = attn + g0 * LLEN;
    float* a1p = a0p + (size_t)8 * LLEN;
    __half2* h0p = g_h + g0 * (LLEN / 2);
    __half2* h1p = h0p + (size_t)8 * (LLEN / 2);

    // ---- Q fragments loaded straight from global into registers (scaled 1/8) ----
    uint32_t qfh[16], qfl[16];
    {
        const float* q0p = qg + g0 * DD;
        const float* q1p = q0p + 8 * DD;
        #pragma unroll
        for (int kc = 0; kc < 4; ++kc) {
            const int c = kc * 16 + qt * 2;
            float2 x0 = *reinterpret_cast<const float2*>(q0p + c);
            float2 x1 = *reinterpret_cast<const float2*>(q1p + c);
            float2 x2 = *reinterpret_cast<const float2*>(q0p + c + 8);
            float2 x3 = *reinterpret_cast<const float2*>(q1p + c + 8);
            split2(x0.x * 0.125f, x0.y * 0.125f, qfh[4 * kc + 0], qfl[4 * kc + 0]);
            split2(x1.x * 0.125f, x1.y * 0.125f, qfh[4 * kc + 1], qfl[4 * kc + 1]);
            split2(x2.x * 0.125f, x2.y * 0.125f, qfh[4 * kc + 2], qfl[4 * kc + 2]);
            split2(x3.x * 0.125f, x3.y * 0.125f, qfh[4 * kc + 3], qfl[4 * kc + 3]);
        }
    }

    // ldmatrix per-lane address components (relative to buffer base)
    const uint32_t boff = (uint32_t)(((((lane >> 4) & 1) * 8) + (lane & 7)) * STRIDE
                                     + ((lane >> 3) & 1) * 16);
    const uint32_t voff = (uint32_t)(((((lane >> 3) & 1) * 8) + (lane & 7)) * STRIDE
                                     + ((lane >> 4) & 1) * 16);

    // preload K tile 0 (bf16 hi/lo) and V tile 0 (fp16)
    {
        float4 r[4];
        load_regs4(kbase, r, tid);
        store_split4(r, smem + OFF_K, smem + OFF_K + BUFB, tid);
        float4 s[4];
        load_regs4(vbase, s, tid);
        store_half4(s, smem + OFF_V, tid);
    }

    float m0 = -3.0e38f, m1 = -3.0e38f, l0 = 0.0f, l1 = 0.0f;

    // ============ PASS 1: per-16col slices: masks -> MMA -> h(fp16)+M_s write + stats ============
    for (int kt = 0; kt < 32; ++kt) {
        const int k0 = kt * 64;
        float4 knext[4];
        if (kt + 1 < 32)
            load_regs4(kbase + (size_t)(k0 + 64) * DD, knext, tid);
        __syncthreads();                 // buf[kt&1] visible; prior readers done

        const int pb = kt & 1;
        const uint32_t kh_a = sb + OFF_K + pb * TILEB + boff;
        const uint32_t kl_a = kh_a + BUFB;

        // mask slice double buffers: [buf][row][j]
        int2 Mb[2][2][2], Db[2][2][2];
        #pragma unroll
        for (int j = 0; j < 2; ++j) {
            const int cb = k0 + j * 8 + qt * 2;
            Mb[0][0][j] = __ldcs(reinterpret_cast<const int2*>(m0p + cb));
            Db[0][0][j] = __ldcs(reinterpret_cast<const int2*>(d0p + cb));
            Mb[0][1][j] = __ldcs(reinterpret_cast<const int2*>(m1p + cb));
            Db[0][1][j] = __ldcs(reinterpret_cast<const int2*>(d1p + cb));
        }

        #pragma unroll
        for (int p = 0; p < 4; ++p) {
            const int cur = p & 1;
            if (p < 3) {
                #pragma unroll
                for (int j = 0; j < 2; ++j) {
                    const int cb = k0 + (2 * (p + 1) + j) * 8 + qt * 2;
                    Mb[cur ^ 1][0][j] = __ldcs(reinterpret_cast<const int2*>(m0p + cb));
                    Db[cur ^ 1][0][j] = __ldcs(reinterpret_cast<const int2*>(d0p + cb));
                    Mb[cur ^ 1][1][j] = __ldcs(reinterpret_cast<const int2*>(m1p + cb));
                    Db[cur ^ 1][1][j] = __ldcs(reinterpret_cast<const int2*>(d1p + cb));
                }
            }

            float acc[2][4];
            #pragma unroll
            for (int j = 0; j < 2; ++j)
                #pragma unroll
                for (int i = 0; i < 4; ++i) acc[j][i] = 0.0f;
            #pragma unroll
            for (int kc = 0; kc < 4; ++kc) {
                uint32_t kh4[4], kl4[4];
                ldsm4(kh_a + p * 16 * STRIDE + kc * 32, kh4);
                ldsm4(kl_a + p * 16 * STRIDE + kc * 32, kl4);
                mma_bf16(acc[0], qfh + 4 * kc, kh4[0], kh4[1]);
                mma_bf16(acc[0], qfh + 4 * kc, kl4[0], kl4[1]);
                mma_bf16(acc[0], qfl + 4 * kc, kh4[0], kh4[1]);
                mma_bf16(acc[1], qfh + 4 * kc, kh4[2], kh4[3]);
                mma_bf16(acc[1], qfh + 4 * kc, kl4[2], kl4[3]);
                mma_bf16(acc[1], qfl + 4 * kc, kh4[2], kh4[3]);
            }

            float smax0 = -3.0e38f, smax1 = -3.0e38f;
            #pragma unroll
            for (int j = 0; j < 2; ++j) {
                float s0 = acc[j][0], s1 = acc[j][1];
                float s2 = acc[j][2], s3 = acc[j][3];
                if (Mb[cur][0][j].x)      s0 = NEG_INF;
                if (Db[cur][0][j].x == 0) s0 = -1.0e32f;
                if (Mb[cur][0][j].y)      s1 = NEG_INF;
                if (Db[cur][0][j].y == 0) s1 = -1.0e32f;
                if (Mb[cur][1][j].x)      s2 = NEG_INF;
                if (Db[cur][1][j].x == 0) s2 = -1.0e32f;
                if (Mb[cur][1][j].y)      s3 = NEG_INF;
                if (Db[cur][1][j].y == 0) s3 = -1.0e32f;
                acc[j][0] = s0; acc[j][1] = s1; acc[j][2] = s2; acc[j][3] = s3;
                smax0 = fmaxf(smax0, fmaxf(s0, s1));
                smax1 = fmaxf(smax1, fmaxf(s2, s3));
            }
            smax0 = fmaxf(smax0, __shfl_xor_sync(0xffffffffu, smax0, 1));
            smax0 = fmaxf(smax0, __shfl_xor_sync(0xffffffffu, smax0, 2));
            smax1 = fmaxf(smax1, __shfl_xor_sync(0xffffffffu, smax1, 1));
            smax1 = fmaxf(smax1, __shfl_xor_sync(0xffffffffu, smax1, 2));
            const float mn0 = fmaxf(m0, smax0);
            const float mn1 = fmaxf(m1, smax1);

            float h00 = __expf(acc[0][0] - mn0), h01 = __expf(acc[0][1] - mn0);
            float h02 = __expf(acc[1][0] - mn0), h03 = __expf(acc[1][1] - mn0);
            float h10 = __expf(acc[0][2] - mn1), h11 = __expf(acc[0][3] - mn1);
            float h12 = __expf(acc[1][2] - mn1), h13 = __expf(acc[1][3] - mn1);

            const int cb0 = k0 + (2 * p) * 8 + qt * 2;
            const int cb1 = cb0 + 8;
            __stcs(h0p + (cb0 >> 1), __floats2half2_rn(h00, h01));
            __stcs(h0p + (cb1 >> 1), __floats2half2_rn(h02, h03));
            __stcs(h1p + (cb0 >> 1), __floats2half2_rn(h10, h11));
            __stcs(h1p + (cb1 >> 1), __floats2half2_rn(h12, h13));
            if (qt == 0) {
                const size_t ms = (size_t)(kt * 4 + p) * NROWSG;
                g_M[ms + g0]     = mn0;
                g_M[ms + g0 + 8] = mn1;
            }

            float e0 = h00 + h01 + h02 + h03;
            float e1 = h10 + h11 + h12 + h13;
            e0 += __shfl_xor_sync(0xffffffffu, e0, 1);
            e0 += __shfl_xor_sync(0xffffffffu, e0, 2);
            e1 += __shfl_xor_sync(0xffffffffu, e1, 1);
            e1 += __shfl_xor_sync(0xffffffffu, e1, 2);
            l0 = l0 * __expf(m0 - mn0) + e0;  m0 = mn0;
            l1 = l1 * __expf(m1 - mn1) + e1;  m1 = mn1;
        }

        if (kt + 1 < 32)
            store_split4(knext, smem + OFF_K + (pb ^ 1) * TILEB,
                         smem + OFF_K + (pb ^ 1) * TILEB + BUFB, tid);
    }

    const float rinv0 = 1.0f / l0;
    const float rinv1 = 1.0f / l1;

    float oacc[8][4];
    #pragma unroll
    for (int nt = 0; nt < 8; ++nt)
        #pragma unroll
        for (int i = 0; i < 4; ++i) oacc[nt][i] = 0.0f;

    // ============ PASS 2: read h(fp16)+M_s -> probs write -> fp16 PV ============
    for (int kt = 0; kt < 32; ++kt) {
        const int k0 = kt * 64;
        float4 vnext[4];
        if (kt + 1 < 32)
            load_regs4(vbase + (size_t)(k0 + 64) * DD, vnext, tid);

        uint32_t Hb[2][4];
        float Mb0[2], Mb1[2];
        {
            const int cA = k0 + qt * 2;
            Hb[0][0] = __ldcs(reinterpret_cast<const uint32_t*>(h0p + (cA >> 1)));
            Hb[0][1] = __ldcs(reinterpret_cast<const uint32_t*>(h0p + ((cA + 8) >> 1)));
            Hb[0][2] = __ldcs(reinterpret_cast<const uint32_t*>(h1p + (cA >> 1)));
            Hb[0][3] = __ldcs(reinterpret_cast<const uint32_t*>(h1p + ((cA + 8) >> 1)));
            const size_t ms = (size_t)(kt * 4) * NROWSG;
            Mb0[0] = __ldcs(&g_M[ms + g0]);
            Mb1[0] = __ldcs(&g_M[ms + g0 + 8]);
        }
        __syncthreads();                 // V buf[kt&1] visible; prior readers done

        const int pb = kt & 1;
        const uint32_t v_a = sb + OFF_V + pb * BUFB + voff;

        #pragma unroll
        for (int kc2 = 0; kc2 < 4; ++kc2) {
            const int cur = kc2 & 1;
            if (kc2 < 3) {
                const int cA = k0 + (kc2 + 1) * 16 + qt * 2;
                Hb[cur ^ 1][0] = __ldcs(reinterpret_cast<const uint32_t*>(h0p + (cA >> 1)));
                Hb[cur ^ 1][1] = __ldcs(reinterpret_cast<const uint32_t*>(h0p + ((cA + 8) >> 1)));
                Hb[cur ^ 1][2] = __ldcs(reinterpret_cast<const uint32_t*>(h1p + (cA >> 1)));
                Hb[cur ^ 1][3] = __ldcs(reinterpret_cast<const uint32_t*>(h1p + ((cA + 8) >> 1)));
                const size_t ms = (size_t)(kt * 4 + kc2 + 1) * NROWSG;
                Mb0[cur ^ 1] = __ldcs(&g_M[ms + g0]);
                Mb1[cur ^ 1] = __ldcs(&g_M[ms + g0 + 8]);
            }

            const float f0 = __expf(Mb0[cur] - m0) * rinv0;
            const float f1 = __expf(Mb1[cur] - m1) * rinv1;

            const int cA = k0 + kc2 * 16 + qt * 2;
            float2 xa = __half22float2(*reinterpret_cast<const __half2*>(&Hb[cur][0]));
            float2 xb = __half22float2(*reinterpret_cast<const __half2*>(&Hb[cur][1]));
            float2 xc = __half22float2(*reinterpret_cast<const __half2*>(&Hb[cur][2]));
            float2 xd = __half22float2(*reinterpret_cast<const __half2*>(&Hb[cur][3]));
            float p00 = xa.x * f0, p01 = xa.y * f0;
            float p02 = xb.x * f0, p03 = xb.y * f0;
            float p10 = xc.x * f1, p11 = xc.y * f1;
            float p12 = xd.x * f1, p13 = xd.y * f1;
            __stcs(reinterpret_cast<float2*>(a0p + cA),     make_float2(p00, p01));
            __stcs(reinterpret_cast<float2*>(a0p + cA + 8), make_float2(p02, p03));
            __stcs(reinterpret_cast<float2*>(a1p + cA),     make_float2(p10, p11));
            __stcs(reinterpret_cast<float2*>(a1p + cA + 8), make_float2(p12, p13));

            // fp16 P fragments (A-layout: row0-klo, row1-klo, row0-khi, row1-khi)
            uint32_t pf[4];
            pf[0] = pack_h2(p00, p01);
            pf[1] = pack_h2(p10, p11);
            pf[2] = pack_h2(p02, p03);
            pf[3] = pack_h2(p12, p13);

            #pragma unroll
            for (int p = 0; p < 4; ++p) {
                uint32_t v4[4];
                ldsm4t(v_a + kc2 * 16 * STRIDE + p * 32, v4);
                mma_f16(oacc[2 * p],     pf, v4[0], v4[1]);
                mma_f16(oacc[2 * p + 1], pf, v4[2], v4[3]);
            }
        }
        if (kt + 1 < 32)
            store_half4(vnext, smem + OFF_V + (pb ^ 1) * BUFB, tid);
    }

    // ---- write output ----
    float* o0 = outp + g0 * DD;
    float* o1 = o0 + (size_t)8 * DD;
    #pragma unroll
    for (int nt = 0; nt < 8; ++nt) {
        const int cb = nt * 8 + qt * 2;
        __stcs(reinterpret_cast<float2*>(o0 + cb), make_float2(oacc[nt][0], oacc[nt][1]));
        __stcs(reinterpret_cast<float2*>(o1 + cb), make_float2(oacc[nt][2], oacc[nt][3]));
    }
}

extern "C" void kernel_launch(void* const* d_in, const int* in_sizes, int n_in,
                              void* d_out, int out_size)
{
    const float* q    = (const float*)d_in[0];
    const float* k    = (const float*)d_in[1];
    const float* v    = (const float*)d_in[2];
    const int*   diag = (const int*)d_in[3];
    const int*   mask = (const int*)d_in[4];

    float* out  = (float*)d_out;                     // [B, L, D]
    float* attn = out + (size_t)BB * LLEN * DD;      // [B, L, L]

    cudaFuncSetAttribute(attn_mma_kernel,
                         cudaFuncAttributeMaxDynamicSharedMemorySize, SMEM_TOTAL);
    dim3 grid(LLEN / TQ, BB);
    attn_mma_kernel<<<grid, NTH, SMEM_TOTAL>>>(q, k, v, diag, mask, out, attn);
}